// round 3
// baseline (speedup 1.0000x reference)
#include <cuda_runtime.h>
#include <cuda_fp16.h>
#include <cstdint>

// ============================================================
// Bahdanau additive attention, GB300 sm_103 (no 'a' features!)
//   dp[b,e]  = dec[b]@w2 + b2 + b1
//   scores   = v . tanh(enc@w1 + dp)     (fused HMMA mma.sync GEMM epilogue)
//   attn     = softmax_s(scores)         (bv dropped: shift-invariant)
//   context  = attn @ enc                (fp32 enc for accuracy)
// ============================================================

#define ENCD 1024
#define NB   32
#define NS   2048
#define MTOT (NB*NS)

// GEMM tile: BM=128, BN=128, BK=64, 3-stage cp.async pipeline, 256 thr (8 warps 4x2)
#define STAGE_BYTES 32768          // A 16KB + B 16KB
#define MISC_OFF    (3*STAGE_BYTES)
#define SMEM_REQ    (MISC_OFF + 2048)
#define NPART 16                   // 8 nt * 2 warp_n partial score slots

// ---------------- device scratch ----------------
__device__ __half g_encH[(size_t)MTOT*ENCD];      // enc fp16, 128MB
__device__ __half g_w1H[(size_t)ENCD*ENCD];       // w1 transposed: [e][d]
__device__ float  g_dp[NB*ENCD];
__device__ float  g_scores_part[NPART][MTOT];     // 4MB
__device__ float  g_attn[NB*NS];
__device__ float  g_ctx_part[16][NB*ENCD];

// ---------------- helpers ----------------
__device__ __forceinline__ uint32_t smem_u32(const void* p) {
    uint32_t a;
    asm("{ .reg .u64 t; cvta.to.shared.u64 t, %1; cvt.u32.u64 %0, t; }" : "=r"(a) : "l"(p));
    return a;
}
#define SWZ128(off) ((off) ^ (((off) >> 3) & 0x70))

__device__ __forceinline__ void cp_async16(uint32_t dst, const void* src) {
    asm volatile("cp.async.cg.shared.global [%0], [%1], 16;" :: "r"(dst), "l"(src) : "memory");
}
#define CP_COMMIT() asm volatile("cp.async.commit_group;" ::: "memory")
#define CP_WAIT1()  asm volatile("cp.async.wait_group 1;" ::: "memory")

__device__ __forceinline__ void ldsm_x4(uint32_t* r, uint32_t addr) {
    asm volatile("ldmatrix.sync.aligned.m8n8.x4.shared.b16 {%0,%1,%2,%3}, [%4];"
                 : "=r"(r[0]), "=r"(r[1]), "=r"(r[2]), "=r"(r[3]) : "r"(addr));
}
__device__ __forceinline__ void ldsm_x2(uint32_t* r, uint32_t addr) {
    asm volatile("ldmatrix.sync.aligned.m8n8.x2.shared.b16 {%0,%1}, [%2];"
                 : "=r"(r[0]), "=r"(r[1]) : "r"(addr));
}
__device__ __forceinline__ void mma16816(float* c, const uint32_t* a, const uint32_t* b) {
    asm volatile(
        "mma.sync.aligned.m16n8k16.row.col.f32.f16.f16.f32 "
        "{%0,%1,%2,%3}, {%4,%5,%6,%7}, {%8,%9}, {%0,%1,%2,%3};"
        : "+f"(c[0]), "+f"(c[1]), "+f"(c[2]), "+f"(c[3])
        : "r"(a[0]), "r"(a[1]), "r"(a[2]), "r"(a[3]), "r"(b[0]), "r"(b[1]));
}

// ============================================================
// 1a. enc fp32 -> fp16
// ============================================================
__global__ void conv_enc_kernel(const float* __restrict__ enc) {
    const float4* in4 = (const float4*)enc;
    uint4* out4 = (uint4*)g_encH;
    int base = blockIdx.x * 256 + threadIdx.x;           // 8192 blocks
    #pragma unroll
    for (int it = 0; it < 4; it++) {
        int o = base + it * 2097152;                     // 8388608 uint4 outs
        float4 a = in4[2 * o];
        float4 b = in4[2 * o + 1];
        __half2 h0 = __floats2half2_rn(a.x, a.y);
        __half2 h1 = __floats2half2_rn(a.z, a.w);
        __half2 h2 = __floats2half2_rn(b.x, b.y);
        __half2 h3 = __floats2half2_rn(b.z, b.w);
        uint4 r;
        r.x = *(const uint32_t*)&h0; r.y = *(const uint32_t*)&h1;
        r.z = *(const uint32_t*)&h2; r.w = *(const uint32_t*)&h3;
        out4[o] = r;
    }
}

// ============================================================
// 1b. w1 transpose -> fp16   g_w1H[e][d] = w1[d][e]
// ============================================================
__global__ void conv_w1_kernel(const float* __restrict__ w1) {
    __shared__ float tile[32][33];
    int dt = blockIdx.x * 32, et = blockIdx.y * 32;
    int tx = threadIdx.x, ty = threadIdx.y;               // 32x8
    #pragma unroll
    for (int i = 0; i < 4; i++)
        tile[ty + i * 8][tx] = w1[(dt + ty + i * 8) * 1024 + et + tx];
    __syncthreads();
    #pragma unroll
    for (int i = 0; i < 4; i++)
        g_w1H[(et + ty + i * 8) * 1024 + dt + tx] = __float2half(tile[tx][ty + i * 8]);
}

// ============================================================
// 2. dp[b][e] = dec[b]@w2 + b2[e] + b1[e]
// ============================================================
__global__ void dp_kernel(const float* __restrict__ dec, const float* __restrict__ w2,
                          const float* __restrict__ b1, const float* __restrict__ b2) {
    __shared__ float dec_s[1024];
    int b  = blockIdx.x >> 3;
    int eb = blockIdx.x & 7;
    int t  = threadIdx.x;       // 128
    #pragma unroll
    for (int i = 0; i < 8; i++) dec_s[t + i * 128] = dec[b * 1024 + t + i * 128];
    __syncthreads();
    int e = eb * 128 + t;
    float acc = 0.f;
    #pragma unroll 8
    for (int d = 0; d < 1024; d++)
        acc += dec_s[d] * w2[d * 1024 + e];
    g_dp[b * 1024 + e] = acc + b1[e] + b2[e];
}

// ============================================================
// 3. Fused GEMM + tanh + v-dot (mma.sync fp16, cp.async 3-stage)
//    grid: 512 mt x 8 nt ; block 256
// ============================================================
__global__ void __launch_bounds__(256, 2)
gemm_kernel(const float* __restrict__ v) {
    extern __shared__ char sm[];
    uint32_t smb = smem_u32(sm);

    const int tid = threadIdx.x;
    const int lane = tid & 31, wid = tid >> 5;
    const int warp_m = wid >> 1, warp_n = wid & 1;        // 4 x 2
    const int mt = blockIdx.x >> 3;                        // 512
    const int nt = blockIdx.x & 7;                         // 8
    const int b  = mt >> 4;                                // 128 rows per mt, 2048/batch

    float* dp_s = (float*)(sm + MISC_OFF);
    float* v_s  = (float*)(sm + MISC_OFF + 512);
    if (tid < 128) {
        dp_s[tid] = g_dp[b * 1024 + nt * 128 + tid];
        v_s[tid]  = v[nt * 128 + tid];
    }

    const int arow = mt * 128;
    const int brow = nt * 128;
    // per-thread cp.async slots: 2048 chunks of 16B per stage (A 1024 + B 1024)
    const int r_  = tid >> 1;                  // 0..127
    const int c0_ = (tid & 1) * 4;             // 0 or 4 (4 chunks each half-row)

    // prologue: stages 0,1
    #pragma unroll
    for (int s = 0; s < 2; s++) {
        uint32_t st = smb + s * STAGE_BYTES;
        #pragma unroll
        for (int c = 0; c < 4; c++) {
            uint32_t off = SWZ128((uint32_t)(r_ * 128 + (c0_ + c) * 16));
            cp_async16(st + off,         &g_encH[(size_t)(arow + r_) * 1024 + s * 64 + (c0_ + c) * 8]);
            cp_async16(st + 16384 + off, &g_w1H[(size_t)(brow + r_) * 1024 + s * 64 + (c0_ + c) * 8]);
        }
        CP_COMMIT();
    }

    float acc[2][8][4];
    #pragma unroll
    for (int t = 0; t < 2; t++)
        #pragma unroll
        for (int j = 0; j < 8; j++)
            #pragma unroll
            for (int q = 0; q < 4; q++) acc[t][j][q] = 0.f;

    // ldmatrix lane addressing (within-stage byte offsets, swizzled)
    const int l15 = lane & 15, lh = lane >> 4;          // A: row, k-half
    const int l7 = lane & 7,  bh = (lane >> 3) & 1;     // B: row, k-half

    for (int ks = 0; ks < 16; ks++) {
        CP_WAIT1();
        __syncthreads();

        if (ks + 2 < 16) {
            const int s = ks + 2;
            uint32_t st = smb + (s % 3) * STAGE_BYTES;
            #pragma unroll
            for (int c = 0; c < 4; c++) {
                uint32_t off = SWZ128((uint32_t)(r_ * 128 + (c0_ + c) * 16));
                cp_async16(st + off,         &g_encH[(size_t)(arow + r_) * 1024 + s * 64 + (c0_ + c) * 8]);
                cp_async16(st + 16384 + off, &g_w1H[(size_t)(brow + r_) * 1024 + s * 64 + (c0_ + c) * 8]);
            }
        }
        CP_COMMIT();

        uint32_t Ast = smb + (ks % 3) * STAGE_BYTES;
        uint32_t Bst = Ast + 16384;
        #pragma unroll
        for (int kk = 0; kk < 4; kk++) {
            uint32_t a0[4], a1[4];
            ldsm_x4(a0, Ast + SWZ128((uint32_t)((warp_m * 32 +      l15) * 128 + kk * 32 + lh * 16)));
            ldsm_x4(a1, Ast + SWZ128((uint32_t)((warp_m * 32 + 16 + l15) * 128 + kk * 32 + lh * 16)));
            #pragma unroll
            for (int j = 0; j < 8; j++) {
                uint32_t bf[2];
                ldsm_x2(bf, Bst + SWZ128((uint32_t)((warp_n * 64 + j * 8 + l7) * 128 + kk * 32 + bh * 16)));
                mma16816(acc[0][j], a0, bf);
                mma16816(acc[1][j], a1, bf);
            }
        }
        __syncthreads();
    }

    // fused epilogue: per-row sum of v[n]*tanh(acc + dp[n])
    #pragma unroll
    for (int t = 0; t < 2; t++) {
        float rs0 = 0.f, rs1 = 0.f;     // rows m_base, m_base+8
        #pragma unroll
        for (int j = 0; j < 8; j++) {
            int nl = warp_n * 64 + j * 8 + (lane & 3) * 2;
            float d0 = dp_s[nl], d1 = dp_s[nl + 1];
            float v0 = v_s[nl],  v1 = v_s[nl + 1];
            float y0, y1, y2, y3;
            asm("tanh.approx.f32 %0, %1;" : "=f"(y0) : "f"(acc[t][j][0] + d0));
            asm("tanh.approx.f32 %0, %1;" : "=f"(y1) : "f"(acc[t][j][1] + d1));
            asm("tanh.approx.f32 %0, %1;" : "=f"(y2) : "f"(acc[t][j][2] + d0));
            asm("tanh.approx.f32 %0, %1;" : "=f"(y3) : "f"(acc[t][j][3] + d1));
            rs0 += v0 * y0 + v1 * y1;
            rs1 += v0 * y2 + v1 * y3;
        }
        rs0 += __shfl_xor_sync(~0u, rs0, 1); rs0 += __shfl_xor_sync(~0u, rs0, 2);
        rs1 += __shfl_xor_sync(~0u, rs1, 1); rs1 += __shfl_xor_sync(~0u, rs1, 2);
        if ((lane & 3) == 0) {
            int m = mt * 128 + warp_m * 32 + t * 16 + (lane >> 2);
            int p = nt * 2 + warp_n;
            g_scores_part[p][m]     = rs0;
            g_scores_part[p][m + 8] = rs1;
        }
    }
}

// ============================================================
// 4. softmax over sequence dim (per batch)
// ============================================================
__global__ void softmax_kernel() {
    __shared__ float red[32];
    __shared__ float stat[2];
    int bq = blockIdx.x;
    int t = threadIdx.x, lane = t & 31, wid = t >> 5;   // 1024 threads
    int base = bq * 2048;
    float s0 = 0.f, s1 = 0.f;
    #pragma unroll
    for (int p = 0; p < NPART; p++) {
        s0 += g_scores_part[p][base + t];
        s1 += g_scores_part[p][base + 1024 + t];
    }
    float mx = fmaxf(s0, s1);
    #pragma unroll
    for (int o = 16; o > 0; o >>= 1) mx = fmaxf(mx, __shfl_xor_sync(~0u, mx, o));
    if (lane == 0) red[wid] = mx;
    __syncthreads();
    if (t < 32) {
        float m2 = red[t];
        #pragma unroll
        for (int o = 16; o > 0; o >>= 1) m2 = fmaxf(m2, __shfl_xor_sync(~0u, m2, o));
        if (t == 0) stat[0] = m2;
    }
    __syncthreads();
    float M = stat[0];
    float e0 = __expf(s0 - M), e1 = __expf(s1 - M);
    float sum = e0 + e1;
    #pragma unroll
    for (int o = 16; o > 0; o >>= 1) sum += __shfl_xor_sync(~0u, sum, o);
    if (lane == 0) red[wid] = sum;
    __syncthreads();
    if (t < 32) {
        float z = red[t];
        #pragma unroll
        for (int o = 16; o > 0; o >>= 1) z += __shfl_xor_sync(~0u, z, o);
        if (t == 0) stat[1] = z;
    }
    __syncthreads();
    float inv = 1.f / stat[1];
    g_attn[base + t]        = e0 * inv;
    g_attn[base + 1024 + t] = e1 * inv;
}

// ============================================================
// 5. context partials over s-chunks (fp32 enc)
// ============================================================
__global__ void context_kernel(const float* __restrict__ enc) {
    __shared__ float attn_s[128];
    int sc = blockIdx.x, eb = blockIdx.y, b = blockIdx.z;
    int t = threadIdx.x;                  // 128
    attn_s[t] = g_attn[b * 2048 + sc * 128 + t];
    __syncthreads();
    int e = eb * 128 + t;
    const float* base = enc + (size_t)(b * 2048 + sc * 128) * 1024 + e;
    float acc = 0.f;
    #pragma unroll 4
    for (int s = 0; s < 128; s++)
        acc += attn_s[s] * base[(size_t)s * 1024];
    g_ctx_part[sc][b * 1024 + e] = acc;
}

// ============================================================
// 6. final reduce -> d_out [32,1024] fp32
// ============================================================
__global__ void reduce_kernel(float* __restrict__ out) {
    int i = blockIdx.x * 256 + threadIdx.x;   // 128 x 256
    float acc = 0.f;
    #pragma unroll
    for (int sc = 0; sc < 16; sc++) acc += g_ctx_part[sc][i];
    out[i] = acc;
}

// ============================================================
extern "C" void kernel_launch(void* const* d_in, const int* in_sizes, int n_in,
                              void* d_out, int out_size) {
    const float* enc = (const float*)d_in[0];
    const float* dec = (const float*)d_in[1];
    const float* w1  = (const float*)d_in[2];
    const float* b1  = (const float*)d_in[3];
    const float* w2  = (const float*)d_in[4];
    const float* b2  = (const float*)d_in[5];
    const float* v   = (const float*)d_in[6];
    // bv (d_in[7]) unused: softmax is shift-invariant.
    float* out = (float*)d_out;

    cudaFuncSetAttribute(gemm_kernel, cudaFuncAttributeMaxDynamicSharedMemorySize, SMEM_REQ);

    conv_enc_kernel<<<8192, 256>>>(enc);
    conv_w1_kernel<<<dim3(32, 32), dim3(32, 8)>>>(w1);
    dp_kernel<<<256, 128>>>(dec, w2, b1, b2);
    gemm_kernel<<<4096, 256, SMEM_REQ>>>(v);
    softmax_kernel<<<32, 1024>>>();
    context_kernel<<<dim3(16, 8, 32), 128>>>(enc);
    reduce_kernel<<<128, 256>>>(out);
}